// round 13
// baseline (speedup 1.0000x reference)
#include <cuda_runtime.h>
#include <cuda_fp16.h>
#include <mma.h>
#include <cstdint>

using namespace nvcuda;

#define Bdim 2
#define Sdim 2048
#define Hdim 16
#define Ddim 64
#define BH   (Bdim * Hdim)       // 32
#define NROWS (BH * Sdim)        // 65536
#define LOG2E 1.4426950408889634f
#define EXPC2 11.544f            // exp2 offset keeps E in fp16 range

// ---------------------------------------------------------------------------
// Scratch (module scope; in-launch allocation is forbidden)
// ---------------------------------------------------------------------------
__device__ __half g_qt  [(size_t)BH * Sdim * Ddim];   // q [bh][s][d] * 0.125*log2e
__device__ __half g_keff[(size_t)BH * Sdim * Ddim];   // (k + r) [bh][s][d], fp16
__device__ __half g_vt  [(size_t)BH * Sdim * Ddim];   // v [bh][s][d], fp16
__device__ float  g_bias[NROWS];                      // log2-domain bias - EXPC2
__device__ float  g_l   [NROWS];                      // per-q-row sum of E
__device__ __half g_e   [(size_t)BH * Sdim * Sdim];   // E = exp2(S2+bias2), fp16

// ---------------------------------------------------------------------------
// 1) transpose + scale + fp16 convert (q pre-scaled into log2 domain)
// ---------------------------------------------------------------------------
__global__ __launch_bounds__(256) void prep_kernel(
    const float* __restrict__ q, const float* __restrict__ k,
    const float* __restrict__ v, const float* __restrict__ r)
{
    int idx = blockIdx.x * 256 + threadIdx.x;        // over B*S*H*D = 2^22
    int d = idx & 63;
    int h = (idx >> 6) & 15;
    int s = (idx >> 10) & 2047;
    int b = idx >> 21;
    int dst = (((b * Hdim + h) * Sdim) + s) * Ddim + d;
    g_qt[dst]   = __float2half_rn(q[idx] * (0.125f * LOG2E));
    g_keff[dst] = __float2half_rn(k[idx] + r[idx]);
    g_vt[dst]   = __float2half_rn(v[idx]);
}

// ---------------------------------------------------------------------------
// 2) per-key bias (log2 domain) + l zeroing
// ---------------------------------------------------------------------------
__global__ __launch_bounds__(256) void bias_kernel(
    const float* __restrict__ k, const float* __restrict__ r,
    const float* __restrict__ r_bias, const float* __restrict__ r_w_bias)
{
    int row = blockIdx.x * 256 + threadIdx.x;        // bh*S + s
    if (row >= NROWS) return;
    int s  = row & 2047;
    int bh = row >> 11;
    int h  = bh & 15;
    int b  = bh >> 4;
    size_t src = ((size_t)(b * Sdim + s) * Hdim + h) * Ddim;
    const float* kp = k + src;
    const float* rp = r + src;
    const float* u  = r_w_bias + h * Ddim;
    const float* w  = r_bias   + h * Ddim;
    float acc = 0.f;
#pragma unroll
    for (int d = 0; d < Ddim; d++) acc += u[d] * kp[d] + w[d] * rp[d];
    g_bias[row] = acc * (0.125f * LOG2E) - EXPC2;
    g_l[row] = 0.f;
}

// ---------------------------------------------------------------------------
// 3) scores + exp2 + row-sums: E = exp2(q.keff + bias2), fp16, masked;
//    l accumulated by atomics. Lower-triangle 128-tiles only.
// ---------------------------------------------------------------------------
__global__ __launch_bounds__(256) void scores_exp_kernel()
{
    const int kt = blockIdx.x, qt = blockIdx.y, bh = blockIdx.z;
    if (kt > qt) return;
    const int q0 = qt * 128, k0 = kt * 128;

    __shared__ __align__(16) char smbuf[2 * 128 * 72 * 2];   // 36864 B
    __shared__ float bs[128];
    __half* Qs = (__half*)smbuf;            // [128][72]
    __half* Ks = Qs + 128 * 72;             // [128][72]
    float*  Cs = (float*)smbuf;             // [128][68] staging (reuse)

    const int t = threadIdx.x;
    const __half* qptr = g_qt   + ((size_t)bh * Sdim + q0) * Ddim;
    const __half* kptr = g_keff + ((size_t)bh * Sdim + k0) * Ddim;
#pragma unroll
    for (int i = 0; i < 4; i++) {
        int idx8 = t + i * 256;             // 1024 uint4 = 128x64 halves
        int row = idx8 >> 3, c8 = (idx8 & 7) * 8;
        *(uint4*)&Qs[row * 72 + c8] = *(const uint4*)&qptr[row * 64 + c8];
        *(uint4*)&Ks[row * 72 + c8] = *(const uint4*)&kptr[row * 64 + c8];
    }
    if (t < 128) bs[t] = g_bias[bh * Sdim + k0 + t];
    __syncthreads();

    const int wid = t >> 5;
    const int wm = wid & 3;        // row group (32 rows)
    const int wn = wid >> 2;       // col group (64 cols)

    wmma::fragment<wmma::accumulator, 16, 16, 16, float> acc[2][4];
#pragma unroll
    for (int i = 0; i < 2; i++)
#pragma unroll
        for (int j = 0; j < 4; j++) wmma::fill_fragment(acc[i][j], 0.f);

#pragma unroll
    for (int kk = 0; kk < 64; kk += 16) {
        wmma::fragment<wmma::matrix_a, 16, 16, 16, __half, wmma::row_major> a[2];
        wmma::fragment<wmma::matrix_b, 16, 16, 16, __half, wmma::col_major> b[4];
#pragma unroll
        for (int i = 0; i < 2; i++)
            wmma::load_matrix_sync(a[i], &Qs[(wm * 32 + i * 16) * 72 + kk], 72);
#pragma unroll
        for (int j = 0; j < 4; j++)
            wmma::load_matrix_sync(b[j], &Ks[(wn * 64 + j * 16) * 72 + kk], 72);
#pragma unroll
        for (int i = 0; i < 2; i++)
#pragma unroll
            for (int j = 0; j < 4; j++)
                wmma::mma_sync(acc[i][j], a[i], b[j], acc[i][j]);
    }
    __syncthreads();   // Qs/Ks no longer needed; region becomes Cs

    const int diag = (kt == qt);
    __half* ebase = g_e + ((size_t)(bh * Sdim) + q0) * Sdim + k0;
    float* lrow = &g_l[bh * Sdim + q0];
#pragma unroll
    for (int half = 0; half < 2; half++) {
        if (wn == half) {
#pragma unroll
            for (int i = 0; i < 2; i++)
#pragma unroll
                for (int j = 0; j < 4; j++)
                    wmma::store_matrix_sync(&Cs[(wm * 32 + i * 16) * 68 + j * 16],
                                            acc[i][j], 68, wmma::mem_row_major);
        }
        __syncthreads();
#pragma unroll
        for (int i = 0; i < 8; i++) {
            int idx4 = t + i * 256;         // 2048 groups of 4 = 128x64
            int row = idx4 >> 4, c4 = (idx4 & 15) * 4;
            int col = half * 64 + c4;
            int vlim = diag ? row : 9999;   // valid: col <= vlim
            float4 v = *(const float4*)&Cs[row * 68 + c4];
            float e0 = (col + 0 <= vlim) ? exp2f(v.x + bs[col + 0]) : 0.f;
            float e1 = (col + 1 <= vlim) ? exp2f(v.y + bs[col + 1]) : 0.f;
            float e2 = (col + 2 <= vlim) ? exp2f(v.z + bs[col + 2]) : 0.f;
            float e3 = (col + 3 <= vlim) ? exp2f(v.w + bs[col + 3]) : 0.f;
            float rs = e0 + e1 + e2 + e3;
            rs += __shfl_xor_sync(0xffffffffu, rs, 1);
            rs += __shfl_xor_sync(0xffffffffu, rs, 2);
            rs += __shfl_xor_sync(0xffffffffu, rs, 4);
            rs += __shfl_xor_sync(0xffffffffu, rs, 8);
            if ((t & 15) == 0) atomicAdd(&lrow[row], rs);
            __half2 h0 = __floats2half2_rn(e0, e1);
            __half2 h1 = __floats2half2_rn(e2, e3);
            uint2 pk = make_uint2(*(uint32_t*)&h0, *(uint32_t*)&h1);
            *(uint2*)&ebase[(size_t)row * Sdim + col] = pk;
        }
        __syncthreads();
    }
}

// ---------------------------------------------------------------------------
// 4) fused pv + normalize: out = (E @ V) * (1/l); while staging each E tile
//    for the MMA, also stream the normalized p = E * (1/l) to P (fp32).
//    E is read exactly once from DRAM.
// ---------------------------------------------------------------------------
__global__ __launch_bounds__(256) void pv_kernel(
    float* __restrict__ out, float* __restrict__ P, int wp)
{
    const int qt = gridDim.x - 1 - blockIdx.x;   // heavy tiles first
    const int bh = blockIdx.y;
    const int q0 = qt * 128;
    const int t = threadIdx.x, wid = t >> 5;

    __shared__ __align__(16) char smbuf[128 * 68 * 4];  // 34816 B
    __shared__ float linv[128];
    __half* Ps = (__half*)smbuf;                // [128][72] = 18432 B
    __half* Vs = Ps + 128 * 72;                 // [64][72]  =  9216 B
    float*  Es = (float*)smbuf;                 // [128][68] epilogue staging

    if (t < 128) linv[t] = 1.0f / g_l[bh * Sdim + q0 + t];
    __syncthreads();

    wmma::fragment<wmma::accumulator, 16, 16, 16, float> acc[4];
#pragma unroll
    for (int j = 0; j < 4; j++) wmma::fill_fragment(acc[j], 0.f);

    const __half* erow = g_e + ((size_t)(bh * Sdim) + q0) * Sdim;
    float* prow = P + ((size_t)(bh * Sdim) + q0) * Sdim;
    const int nchunks = 2 * qt + 2;
    for (int kc = 0; kc < nchunks; kc++) {
        int k0 = kc * 64;
        const __half* vp = g_vt + ((size_t)bh * Sdim + k0) * Ddim;
        __syncthreads();
#pragma unroll
        for (int i = 0; i < 4; i++) {
            int idx8 = t + i * 256;             // 1024 uint4 = 128x64 halves
            int row = idx8 >> 3, c8 = (idx8 & 7) * 8;
            uint4 pk = *(const uint4*)&erow[(size_t)row * Sdim + k0 + c8];
            *(uint4*)&Ps[row * 72 + c8] = pk;
            if (wp) {                           // stream normalized p
                float s = linv[row];
                __half2 h0 = *(__half2*)&pk.x;
                __half2 h1 = *(__half2*)&pk.y;
                __half2 h2 = *(__half2*)&pk.z;
                __half2 h3 = *(__half2*)&pk.w;
                float4 f0, f1;
                f0.x = __low2float(h0) * s;  f0.y = __high2float(h0) * s;
                f0.z = __low2float(h1) * s;  f0.w = __high2float(h1) * s;
                f1.x = __low2float(h2) * s;  f1.y = __high2float(h2) * s;
                f1.z = __low2float(h3) * s;  f1.w = __high2float(h3) * s;
                float* dst = &prow[(size_t)row * Sdim + k0 + c8];
                *(float4*)(dst)     = f0;
                *(float4*)(dst + 4) = f1;
            }
        }
#pragma unroll
        for (int i = 0; i < 2; i++) {
            int idx8 = t + i * 256;             // 512 uint4 = 64x64 halves
            int row = idx8 >> 3, c8 = (idx8 & 7) * 8;
            *(uint4*)&Vs[row * 72 + c8] = *(const uint4*)&vp[row * 64 + c8];
        }
        __syncthreads();

#pragma unroll
        for (int kk = 0; kk < 64; kk += 16) {
            wmma::fragment<wmma::matrix_a, 16, 16, 16, __half, wmma::row_major> a;
            wmma::fragment<wmma::matrix_b, 16, 16, 16, __half, wmma::row_major> b[4];
            wmma::load_matrix_sync(a, &Ps[(wid * 16) * 72 + kk], 72);
#pragma unroll
            for (int j = 0; j < 4; j++)
                wmma::load_matrix_sync(b[j], &Vs[kk * 72 + j * 16], 72);
#pragma unroll
            for (int j = 0; j < 4; j++)
                wmma::mma_sync(acc[j], a, b[j], acc[j]);
        }
    }

    __syncthreads();   // Ps/Vs dead; reuse as Es
#pragma unroll
    for (int j = 0; j < 4; j++)
        wmma::store_matrix_sync(&Es[(wid * 16) * 68 + j * 16], acc[j],
                                68, wmma::mem_row_major);
    __syncthreads();

    float* op = out + ((size_t)bh * Sdim + q0) * Ddim;
#pragma unroll
    for (int i = 0; i < 8; i++) {
        int idx4 = t + i * 256;                 // 2048 float4 = 128x64
        int row = idx4 >> 4, c4 = (idx4 & 15) * 4;
        float4 v = *(const float4*)&Es[row * 68 + c4];
        float s = linv[row];
        v.x *= s; v.y *= s; v.z *= s; v.w *= s;
        *(float4*)&op[(size_t)row * Ddim + c4] = v;
    }
}

// ---------------------------------------------------------------------------
// 5) zfill: zero the masked (upper-triangle) tiles; no data dependencies.
// ---------------------------------------------------------------------------
__global__ __launch_bounds__(256) void zfill_kernel(float* __restrict__ P)
{
    const int kt = blockIdx.x, qt = blockIdx.y, bh = blockIdx.z;
    if (kt <= qt) return;                        // only masked tiles
    const int t = threadIdx.x;
    long long pbase = ((long long)(bh * Sdim) + qt * 128) * Sdim + kt * 128;
    float4 z = make_float4(0.f, 0.f, 0.f, 0.f);
#pragma unroll
    for (int i = 0; i < 16; i++) {
        int idx4 = t + i * 256;                  // 4096 float4 = 128x128
        int row = idx4 >> 5, c4 = (idx4 & 31) * 4;
        *(float4*)&P[pbase + (long long)row * Sdim + c4] = z;
    }
}

// ---------------------------------------------------------------------------
extern "C" void kernel_launch(void* const* d_in, const int* in_sizes, int n_in,
                              void* d_out, int out_size)
{
    const float* q   = (const float*)d_in[0];
    const float* k   = (const float*)d_in[1];
    const float* v   = (const float*)d_in[2];
    const float* r   = (const float*)d_in[3];
    const float* rb  = (const float*)d_in[4];   // r_bias
    const float* rwb = (const float*)d_in[5];   // r_w_bias
    // d_in[6]: causal mask (structure known, not read)

    float* out = (float*)d_out;
    long long out_elems = (long long)BH * Sdim * Ddim;            // 4,194,304
    long long p_elems   = (long long)BH * Sdim * (long long)Sdim; // 134,217,728

    float* P = out;                 // dummy (unused when wp == 0)
    int p_is_output = 0;
    if ((long long)out_size >= out_elems + p_elems) {
        P = out + out_elems;        // p_attn is part of the output
        p_is_output = 1;
    }

    static cudaStream_t s2 = nullptr, s3 = nullptr;
    static cudaEvent_t evFork = nullptr, evA = nullptr, evZ = nullptr;
    if (!s2) {
        cudaStreamCreateWithFlags(&s2, cudaStreamNonBlocking);
        cudaStreamCreateWithFlags(&s3, cudaStreamNonBlocking);
        cudaEventCreateWithFlags(&evFork, cudaEventDisableTiming);
        cudaEventCreateWithFlags(&evA, cudaEventDisableTiming);
        cudaEventCreateWithFlags(&evZ, cudaEventDisableTiming);
    }

    dim3 tgrid(Sdim / 128, Sdim / 128, BH);   // (ktile, qtile, bh)
    dim3 pvgrid(Sdim / 128, BH);

    // Fork s2 (bias) and s3 (zfill) off the capture-origin stream.
    cudaEventRecord(evFork, 0);
    cudaStreamWaitEvent(s2, evFork, 0);
    bias_kernel<<<NROWS / 256, 256, 0, s2>>>(k, r, rb, rwb);
    cudaEventRecord(evA, s2);

    if (p_is_output) {
        cudaStreamWaitEvent(s3, evFork, 0);
        zfill_kernel<<<tgrid, 256, 0, s3>>>(P);   // no deps; overlaps prep+scores
        cudaEventRecord(evZ, s3);
    }

    prep_kernel<<<(Bdim * Sdim * Hdim * Ddim) / 256, 256>>>(q, k, v, r);
    cudaStreamWaitEvent(0, evA, 0);              // scores needs bias + l zeroed

    scores_exp_kernel<<<tgrid, 256>>>();

    pv_kernel<<<pvgrid, 256>>>(out, P, p_is_output);

    if (p_is_output) cudaStreamWaitEvent(0, evZ, 0);
}

// round 14
// speedup vs baseline: 1.1086x; 1.1086x over previous
#include <cuda_runtime.h>
#include <cuda_fp16.h>
#include <mma.h>
#include <cstdint>

using namespace nvcuda;

#define Bdim 2
#define Sdim 2048
#define Hdim 16
#define Ddim 64
#define BH   (Bdim * Hdim)       // 32
#define NROWS (BH * Sdim)        // 65536
#define LOG2E 1.4426950408889634f
#define QSC   (0.125f * LOG2E)
#define EXPC2 11.544f            // exp2 offset keeps E in fp16 range

// ---------------------------------------------------------------------------
// Scratch (module scope; in-launch allocation is forbidden)
// ---------------------------------------------------------------------------
__device__ __half g_vt  [(size_t)BH * Sdim * Ddim];   // v [bh][s][d], fp16
__device__ float  g_bias[NROWS];                      // log2-domain bias - EXPC2
__device__ float  g_l   [NROWS];                      // per-q-row sum of E
__device__ __half g_e   [(size_t)BH * Sdim * Sdim];   // E = exp2(S2+bias2), fp16
__device__ float  g_part[2][(size_t)BH * Sdim * Ddim]; // pv partial sums

// ---------------------------------------------------------------------------
// 1) v transpose + fp16 convert (only v needs pre-staging now)
// ---------------------------------------------------------------------------
__global__ __launch_bounds__(256) void vprep_kernel(const float* __restrict__ v)
{
    int idx = blockIdx.x * 256 + threadIdx.x;        // over B*S*H*D = 2^22
    int d = idx & 63;
    int h = (idx >> 6) & 15;
    int s = (idx >> 10) & 2047;
    int b = idx >> 21;
    g_vt[(((b * Hdim + h) * Sdim) + s) * Ddim + d] = __float2half_rn(v[idx]);
}

// ---------------------------------------------------------------------------
// 2) per-key bias (log2 domain) + l zeroing
// ---------------------------------------------------------------------------
__global__ __launch_bounds__(256) void bias_kernel(
    const float* __restrict__ k, const float* __restrict__ r,
    const float* __restrict__ r_bias, const float* __restrict__ r_w_bias)
{
    int row = blockIdx.x * 256 + threadIdx.x;        // bh*S + s
    if (row >= NROWS) return;
    int s  = row & 2047;
    int bh = row >> 11;
    int h  = bh & 15;
    int b  = bh >> 4;
    size_t src = ((size_t)(b * Sdim + s) * Hdim + h) * Ddim;
    const float* kp = k + src;
    const float* rp = r + src;
    const float* u  = r_w_bias + h * Ddim;
    const float* w  = r_bias   + h * Ddim;
    float acc = 0.f;
#pragma unroll
    for (int d = 0; d < Ddim; d++) acc += u[d] * kp[d] + w[d] * rp[d];
    g_bias[row] = acc * QSC - EXPC2;
    g_l[row] = 0.f;
}

// ---------------------------------------------------------------------------
// 3) scores + exp2 + row-sums, reading RAW q/k/r (fp32 -> fp16 in registers,
//    identical arithmetic to the old prep). E fp16, masked; l via atomics.
//    Lower-triangle 128-tiles only.
// ---------------------------------------------------------------------------
__global__ __launch_bounds__(256) void scores_exp_kernel(
    const float* __restrict__ q, const float* __restrict__ kg,
    const float* __restrict__ rg)
{
    const int kt = blockIdx.x, qt = blockIdx.y, bh = blockIdx.z;
    if (kt > qt) return;
    const int q0 = qt * 128, k0 = kt * 128;
    const int b = bh >> 4, h = bh & 15;

    __shared__ __align__(16) char smbuf[2 * 128 * 72 * 2];   // 36864 B
    __shared__ float bs[128];
    __half* Qs = (__half*)smbuf;            // [128][72]
    __half* Ks = Qs + 128 * 72;             // [128][72]
    float*  Cs = (float*)smbuf;             // [128][68] staging (reuse)

    const int t = threadIdx.x;
#pragma unroll
    for (int i = 0; i < 4; i++) {
        int idx8 = t + i * 256;             // 1024 groups of 8 halves = 128x64
        int row = idx8 >> 3, c8 = (idx8 & 7) * 8;
        // Q row: global s = q0 + row
        size_t qoff = ((size_t)(b * Sdim + q0 + row) * Hdim + h) * Ddim + c8;
        float4 a0 = *(const float4*)&q[qoff];
        float4 a1 = *(const float4*)&q[qoff + 4];
        __half2 q0h = __floats2half2_rn(a0.x * QSC, a0.y * QSC);
        __half2 q1h = __floats2half2_rn(a0.z * QSC, a0.w * QSC);
        __half2 q2h = __floats2half2_rn(a1.x * QSC, a1.y * QSC);
        __half2 q3h = __floats2half2_rn(a1.z * QSC, a1.w * QSC);
        uint4 qp = make_uint4(*(uint32_t*)&q0h, *(uint32_t*)&q1h,
                              *(uint32_t*)&q2h, *(uint32_t*)&q3h);
        *(uint4*)&Qs[row * 72 + c8] = qp;
        // K row: keff = k + r, global s = k0 + row
        size_t koff = ((size_t)(b * Sdim + k0 + row) * Hdim + h) * Ddim + c8;
        float4 k0f = *(const float4*)&kg[koff];
        float4 k1f = *(const float4*)&kg[koff + 4];
        float4 r0f = *(const float4*)&rg[koff];
        float4 r1f = *(const float4*)&rg[koff + 4];
        __half2 k0h = __floats2half2_rn(k0f.x + r0f.x, k0f.y + r0f.y);
        __half2 k1h = __floats2half2_rn(k0f.z + r0f.z, k0f.w + r0f.w);
        __half2 k2h = __floats2half2_rn(k1f.x + r1f.x, k1f.y + r1f.y);
        __half2 k3h = __floats2half2_rn(k1f.z + r1f.z, k1f.w + r1f.w);
        uint4 kp = make_uint4(*(uint32_t*)&k0h, *(uint32_t*)&k1h,
                              *(uint32_t*)&k2h, *(uint32_t*)&k3h);
        *(uint4*)&Ks[row * 72 + c8] = kp;
    }
    if (t < 128) bs[t] = g_bias[bh * Sdim + k0 + t];
    __syncthreads();

    const int wid = t >> 5;
    const int wm = wid & 3;        // row group (32 rows)
    const int wn = wid >> 2;       // col group (64 cols)

    wmma::fragment<wmma::accumulator, 16, 16, 16, float> acc[2][4];
#pragma unroll
    for (int i = 0; i < 2; i++)
#pragma unroll
        for (int j = 0; j < 4; j++) wmma::fill_fragment(acc[i][j], 0.f);

#pragma unroll
    for (int kk = 0; kk < 64; kk += 16) {
        wmma::fragment<wmma::matrix_a, 16, 16, 16, __half, wmma::row_major> a[2];
        wmma::fragment<wmma::matrix_b, 16, 16, 16, __half, wmma::col_major> b2[4];
#pragma unroll
        for (int i = 0; i < 2; i++)
            wmma::load_matrix_sync(a[i], &Qs[(wm * 32 + i * 16) * 72 + kk], 72);
#pragma unroll
        for (int j = 0; j < 4; j++)
            wmma::load_matrix_sync(b2[j], &Ks[(wn * 64 + j * 16) * 72 + kk], 72);
#pragma unroll
        for (int i = 0; i < 2; i++)
#pragma unroll
            for (int j = 0; j < 4; j++)
                wmma::mma_sync(acc[i][j], a[i], b2[j], acc[i][j]);
    }
    __syncthreads();   // Qs/Ks no longer needed; region becomes Cs

    const int diag = (kt == qt);
    __half* ebase = g_e + ((size_t)(bh * Sdim) + q0) * Sdim + k0;
    float* lrow = &g_l[bh * Sdim + q0];
#pragma unroll
    for (int half = 0; half < 2; half++) {
        if (wn == half) {
#pragma unroll
            for (int i = 0; i < 2; i++)
#pragma unroll
                for (int j = 0; j < 4; j++)
                    wmma::store_matrix_sync(&Cs[(wm * 32 + i * 16) * 68 + j * 16],
                                            acc[i][j], 68, wmma::mem_row_major);
        }
        __syncthreads();
#pragma unroll
        for (int i = 0; i < 8; i++) {
            int idx4 = t + i * 256;         // 2048 groups of 4 = 128x64
            int row = idx4 >> 4, c4 = (idx4 & 15) * 4;
            int col = half * 64 + c4;
            int vlim = diag ? row : 9999;   // valid: col <= vlim
            float4 v = *(const float4*)&Cs[row * 68 + c4];
            float e0 = (col + 0 <= vlim) ? exp2f(v.x + bs[col + 0]) : 0.f;
            float e1 = (col + 1 <= vlim) ? exp2f(v.y + bs[col + 1]) : 0.f;
            float e2 = (col + 2 <= vlim) ? exp2f(v.z + bs[col + 2]) : 0.f;
            float e3 = (col + 3 <= vlim) ? exp2f(v.w + bs[col + 3]) : 0.f;
            float rs = e0 + e1 + e2 + e3;
            rs += __shfl_xor_sync(0xffffffffu, rs, 1);
            rs += __shfl_xor_sync(0xffffffffu, rs, 2);
            rs += __shfl_xor_sync(0xffffffffu, rs, 4);
            rs += __shfl_xor_sync(0xffffffffu, rs, 8);
            if ((t & 15) == 0) atomicAdd(&lrow[row], rs);
            __half2 h0 = __floats2half2_rn(e0, e1);
            __half2 h1 = __floats2half2_rn(e2, e3);
            uint2 pk = make_uint2(*(uint32_t*)&h0, *(uint32_t*)&h1);
            *(uint2*)&ebase[(size_t)row * Sdim + col] = pk;
        }
        __syncthreads();
    }
}

// ---------------------------------------------------------------------------
// 4) pv partial: g_part[z] = E_halfrange @ V (unscaled). z splits the k-range
//    in 2 to halve the triangular imbalance; no atomics.
// ---------------------------------------------------------------------------
__global__ __launch_bounds__(256) void pv_kernel()
{
    const int qt = gridDim.x - 1 - blockIdx.x;   // heavy tiles first
    const int bh = blockIdx.y;
    const int half = blockIdx.z;
    const int q0 = qt * 128;
    const int t = threadIdx.x, wid = t >> 5;

    __shared__ __align__(16) char smbuf[128 * 68 * 4];  // 34816 B
    __half* Ps = (__half*)smbuf;                // [128][72] = 18432 B
    __half* Vs = Ps + 128 * 72;                 // [64][72]  =  9216 B
    float*  Es = (float*)smbuf;                 // [128][68] epilogue staging

    wmma::fragment<wmma::accumulator, 16, 16, 16, float> acc[4];
#pragma unroll
    for (int j = 0; j < 4; j++) wmma::fill_fragment(acc[j], 0.f);

    const __half* erow = g_e + ((size_t)(bh * Sdim) + q0) * Sdim;
    const int nchunks = 2 * qt + 2;              // always even
    const int c_lo = half * (nchunks / 2);
    const int c_hi = c_lo + nchunks / 2;
    for (int kc = c_lo; kc < c_hi; kc++) {
        int k0 = kc * 64;
        const __half* vp = g_vt + ((size_t)bh * Sdim + k0) * Ddim;
        __syncthreads();
#pragma unroll
        for (int i = 0; i < 4; i++) {
            int idx8 = t + i * 256;             // 1024 uint4 = 128x64 halves
            int row = idx8 >> 3, c8 = (idx8 & 7) * 8;
            *(uint4*)&Ps[row * 72 + c8] =
                *(const uint4*)&erow[(size_t)row * Sdim + k0 + c8];
        }
#pragma unroll
        for (int i = 0; i < 2; i++) {
            int idx8 = t + i * 256;             // 512 uint4 = 64x64 halves
            int row = idx8 >> 3, c8 = (idx8 & 7) * 8;
            *(uint4*)&Vs[row * 72 + c8] = *(const uint4*)&vp[row * 64 + c8];
        }
        __syncthreads();

#pragma unroll
        for (int kk = 0; kk < 64; kk += 16) {
            wmma::fragment<wmma::matrix_a, 16, 16, 16, __half, wmma::row_major> a;
            wmma::fragment<wmma::matrix_b, 16, 16, 16, __half, wmma::row_major> b[4];
            wmma::load_matrix_sync(a, &Ps[(wid * 16) * 72 + kk], 72);
#pragma unroll
            for (int j = 0; j < 4; j++)
                wmma::load_matrix_sync(b[j], &Vs[kk * 72 + j * 16], 72);
#pragma unroll
            for (int j = 0; j < 4; j++)
                wmma::mma_sync(acc[j], a, b[j], acc[j]);
        }
    }

    __syncthreads();   // Ps/Vs dead; reuse as Es
#pragma unroll
    for (int j = 0; j < 4; j++)
        wmma::store_matrix_sync(&Es[(wid * 16) * 68 + j * 16], acc[j],
                                68, wmma::mem_row_major);
    __syncthreads();

    float* op = g_part[half] + ((size_t)bh * Sdim + q0) * Ddim;
#pragma unroll
    for (int i = 0; i < 8; i++) {
        int idx4 = t + i * 256;                 // 2048 float4 = 128x64
        int row = idx4 >> 4, c4 = (idx4 & 15) * 4;
        *(float4*)&op[(size_t)row * Ddim + c4] =
            *(const float4*)&Es[row * 68 + c4];
    }
}

// ---------------------------------------------------------------------------
// 4b) reduce: out = (part0 + part1) / l
// ---------------------------------------------------------------------------
__global__ __launch_bounds__(256) void reduce_kernel(float* __restrict__ out)
{
    size_t id4 = (size_t)blockIdx.x * 256 + threadIdx.x;   // one per float4
    int rowidx = (int)(id4 >> 4);                          // D=64 -> 16 f4/row
    float s = 1.0f / g_l[rowidx];
    float4 a = *(const float4*)&g_part[0][id4 * 4];
    float4 b = *(const float4*)&g_part[1][id4 * 4];
    float4 v;
    v.x = (a.x + b.x) * s;
    v.y = (a.y + b.y) * s;
    v.z = (a.z + b.z) * s;
    v.w = (a.w + b.w) * s;
    *(float4*)&out[id4 * 4] = v;
}

// ---------------------------------------------------------------------------
// 5a) zfill: zero the masked (upper-triangle) tiles; no data dependencies.
// ---------------------------------------------------------------------------
__global__ __launch_bounds__(256) void zfill_kernel(float* __restrict__ P)
{
    const int kt = blockIdx.x, qt = blockIdx.y, bh = blockIdx.z;
    if (kt <= qt) return;                        // only masked tiles
    const int t = threadIdx.x;
    long long pbase = ((long long)(bh * Sdim) + qt * 128) * Sdim + kt * 128;
    float4 z = make_float4(0.f, 0.f, 0.f, 0.f);
#pragma unroll
    for (int i = 0; i < 16; i++) {
        int idx4 = t + i * 256;                  // 4096 float4 = 128x128
        int row = idx4 >> 5, c4 = (idx4 & 31) * 4;
        *(float4*)&P[pbase + (long long)row * Sdim + c4] = z;
    }
}

// ---------------------------------------------------------------------------
// 5b) normalize: p = E * (1/l) (fp16 -> fp32), lower-triangle tiles only.
// ---------------------------------------------------------------------------
__global__ __launch_bounds__(256) void normalize_kernel(float* __restrict__ P)
{
    const int kt = blockIdx.x, qt = blockIdx.y, bh = blockIdx.z;
    if (kt > qt) return;
    const int q0 = qt * 128, k0 = kt * 128;
    const int t = threadIdx.x;
    long long pbase = ((long long)(bh * Sdim) + q0) * Sdim + k0;

    __shared__ float linv[128];
    if (t < 128) linv[t] = 1.0f / g_l[bh * Sdim + q0 + t];
    __syncthreads();

    const __half* ebase = g_e + ((size_t)(bh * Sdim) + q0) * Sdim + k0;
#pragma unroll
    for (int i = 0; i < 16; i++) {
        int idx4 = t + i * 256;                 // 4096 float4 = 128x128
        int row = idx4 >> 5, c4 = (idx4 & 31) * 4;
        uint2 pk = *(const uint2*)&ebase[(size_t)row * Sdim + c4];
        __half2 h0 = *(__half2*)&pk.x;
        __half2 h1 = *(__half2*)&pk.y;
        float s = linv[row];
        float4 v;
        v.x = __low2float(h0)  * s;
        v.y = __high2float(h0) * s;
        v.z = __low2float(h1)  * s;
        v.w = __high2float(h1) * s;
        *(float4*)&P[pbase + (long long)row * Sdim + c4] = v;
    }
}

// ---------------------------------------------------------------------------
extern "C" void kernel_launch(void* const* d_in, const int* in_sizes, int n_in,
                              void* d_out, int out_size)
{
    const float* q   = (const float*)d_in[0];
    const float* k   = (const float*)d_in[1];
    const float* v   = (const float*)d_in[2];
    const float* r   = (const float*)d_in[3];
    const float* rb  = (const float*)d_in[4];   // r_bias
    const float* rwb = (const float*)d_in[5];   // r_w_bias
    // d_in[6]: causal mask (structure known, not read)

    float* out = (float*)d_out;
    long long out_elems = (long long)BH * Sdim * Ddim;            // 4,194,304
    long long p_elems   = (long long)BH * Sdim * (long long)Sdim; // 134,217,728

    float* P = nullptr;
    int p_is_output = 0;
    if ((long long)out_size >= out_elems + p_elems) {
        P = out + out_elems;          // p_attn is part of the output
        p_is_output = 1;
    }

    static cudaStream_t s2 = nullptr, s3 = nullptr;
    static cudaEvent_t evFork = nullptr, evA = nullptr, evZ = nullptr,
                       evS = nullptr, evN = nullptr;
    if (!s2) {
        cudaStreamCreateWithFlags(&s2, cudaStreamNonBlocking);
        cudaStreamCreateWithFlags(&s3, cudaStreamNonBlocking);
        cudaEventCreateWithFlags(&evFork, cudaEventDisableTiming);
        cudaEventCreateWithFlags(&evA, cudaEventDisableTiming);
        cudaEventCreateWithFlags(&evZ, cudaEventDisableTiming);
        cudaEventCreateWithFlags(&evS, cudaEventDisableTiming);
        cudaEventCreateWithFlags(&evN, cudaEventDisableTiming);
    }

    dim3 tgrid(Sdim / 128, Sdim / 128, BH);   // (ktile, qtile, bh)
    dim3 pvgrid(Sdim / 128, BH, 2);           // pv: k-range split in 2

    // Fork s2 (bias) and s3 (zfill) off the capture-origin stream.
    cudaEventRecord(evFork, 0);
    cudaStreamWaitEvent(s2, evFork, 0);
    bias_kernel<<<NROWS / 256, 256, 0, s2>>>(k, r, rb, rwb);
    cudaEventRecord(evA, s2);

    if (p_is_output) {
        cudaStreamWaitEvent(s3, evFork, 0);
        zfill_kernel<<<tgrid, 256, 0, s3>>>(P);   // no deps; overlaps scores
        cudaEventRecord(evZ, s3);
    }

    vprep_kernel<<<(Bdim * Sdim * Hdim * Ddim) / 256, 256>>>(v);
    cudaStreamWaitEvent(0, evA, 0);              // scores needs bias + l zeroed

    scores_exp_kernel<<<tgrid, 256>>>(q, k, r);

    if (p_is_output) {
        cudaEventRecord(evS, 0);
        cudaStreamWaitEvent(s2, evS, 0);
        normalize_kernel<<<tgrid, 256, 0, s2>>>(P);   // ∥ with pv
        cudaEventRecord(evN, s2);
    }

    pv_kernel<<<pvgrid, 256>>>();
    reduce_kernel<<<(unsigned)(out_elems / 4 / 256), 256>>>(out);

    if (p_is_output) {
        cudaStreamWaitEvent(0, evN, 0);
        cudaStreamWaitEvent(0, evZ, 0);
    }
}

// round 15
// speedup vs baseline: 1.1780x; 1.0626x over previous
#include <cuda_runtime.h>
#include <cuda_fp16.h>
#include <mma.h>
#include <cstdint>

using namespace nvcuda;

#define Bdim 2
#define Sdim 2048
#define Hdim 16
#define Ddim 64
#define BH   (Bdim * Hdim)       // 32
#define NROWS (BH * Sdim)        // 65536
#define LOG2E 1.4426950408889634f
#define EXPC2 11.544f            // exp2 offset keeps E in fp16 range

// ---------------------------------------------------------------------------
// Scratch (module scope; in-launch allocation is forbidden)
// ---------------------------------------------------------------------------
__device__ __half g_qt  [(size_t)BH * Sdim * Ddim];   // q [bh][s][d] * 0.125*log2e
__device__ __half g_keff[(size_t)BH * Sdim * Ddim];   // (k + r) [bh][s][d], fp16
__device__ __half g_vt  [(size_t)BH * Sdim * Ddim];   // v [bh][s][d], fp16
__device__ float  g_bias[NROWS];                      // log2-domain bias - EXPC2
__device__ float  g_l   [NROWS];                      // per-q-row sum of E
__device__ __half g_e   [(size_t)BH * Sdim * Sdim];   // E = exp2(S2+bias2), fp16

// ---------------------------------------------------------------------------
// 1) transpose + scale + fp16 convert (q pre-scaled into log2 domain)
// ---------------------------------------------------------------------------
__global__ __launch_bounds__(256) void prep_kernel(
    const float* __restrict__ q, const float* __restrict__ k,
    const float* __restrict__ v, const float* __restrict__ r)
{
    int idx = blockIdx.x * 256 + threadIdx.x;        // over B*S*H*D = 2^22
    int d = idx & 63;
    int h = (idx >> 6) & 15;
    int s = (idx >> 10) & 2047;
    int b = idx >> 21;
    int dst = (((b * Hdim + h) * Sdim) + s) * Ddim + d;
    g_qt[dst]   = __float2half_rn(q[idx] * (0.125f * LOG2E));
    g_keff[dst] = __float2half_rn(k[idx] + r[idx]);
    g_vt[dst]   = __float2half_rn(v[idx]);
}

// ---------------------------------------------------------------------------
// 2) per-key bias (log2 domain) + l zeroing
// ---------------------------------------------------------------------------
__global__ __launch_bounds__(256) void bias_kernel(
    const float* __restrict__ k, const float* __restrict__ r,
    const float* __restrict__ r_bias, const float* __restrict__ r_w_bias)
{
    int row = blockIdx.x * 256 + threadIdx.x;        // bh*S + s
    if (row >= NROWS) return;
    int s  = row & 2047;
    int bh = row >> 11;
    int h  = bh & 15;
    int b  = bh >> 4;
    size_t src = ((size_t)(b * Sdim + s) * Hdim + h) * Ddim;
    const float* kp = k + src;
    const float* rp = r + src;
    const float* u  = r_w_bias + h * Ddim;
    const float* w  = r_bias   + h * Ddim;
    float acc = 0.f;
#pragma unroll
    for (int d = 0; d < Ddim; d++) acc += u[d] * kp[d] + w[d] * rp[d];
    g_bias[row] = acc * (0.125f * LOG2E) - EXPC2;
    g_l[row] = 0.f;
}

// ---------------------------------------------------------------------------
// 3) scores + exp2 + row-sums on 64x64 tiles: E = exp2(q.keff + bias2), fp16,
//    masked; l via atomics. 128 threads, 4 warps x (16x64) warp tiles.
//    High occupancy (6 CTAs/SM) to fix the latency-bound profile.
// ---------------------------------------------------------------------------
__global__ __launch_bounds__(128, 6) void scores_exp_kernel()
{
    const int kt = blockIdx.x, qt = blockIdx.y, bh = blockIdx.z;
    if (kt > qt) return;
    const int q0 = qt * 64, k0 = kt * 64;
    const int t = threadIdx.x, wid = t >> 5;

    __shared__ __align__(16) char smbuf[2 * 64 * 72 * 2];   // 18432 B
    __shared__ float bs[64];
    __half* Qs = (__half*)smbuf;            // [64][72]
    __half* Ks = Qs + 64 * 72;              // [64][72]
    float*  Cs = (float*)smbuf;             // [64][68] staging = 17408 B (fits)

    const __half* qptr = g_qt   + ((size_t)bh * Sdim + q0) * Ddim;
    const __half* kptr = g_keff + ((size_t)bh * Sdim + k0) * Ddim;
#pragma unroll
    for (int i = 0; i < 4; i++) {
        int idx8 = t + i * 128;             // 512 uint4 = 64x64 halves
        int row = idx8 >> 3, c8 = (idx8 & 7) * 8;
        *(uint4*)&Qs[row * 72 + c8] = *(const uint4*)&qptr[row * 64 + c8];
        *(uint4*)&Ks[row * 72 + c8] = *(const uint4*)&kptr[row * 64 + c8];
    }
    if (t < 64) bs[t] = g_bias[bh * Sdim + k0 + t];
    __syncthreads();

    wmma::fragment<wmma::accumulator, 16, 16, 16, float> acc[4];
#pragma unroll
    for (int j = 0; j < 4; j++) wmma::fill_fragment(acc[j], 0.f);

#pragma unroll
    for (int kk = 0; kk < 64; kk += 16) {
        wmma::fragment<wmma::matrix_a, 16, 16, 16, __half, wmma::row_major> a;
        wmma::fragment<wmma::matrix_b, 16, 16, 16, __half, wmma::col_major> b[4];
        wmma::load_matrix_sync(a, &Qs[(wid * 16) * 72 + kk], 72);
#pragma unroll
        for (int j = 0; j < 4; j++)
            wmma::load_matrix_sync(b[j], &Ks[(j * 16) * 72 + kk], 72);
#pragma unroll
        for (int j = 0; j < 4; j++)
            wmma::mma_sync(acc[j], a, b[j], acc[j]);
    }
    __syncthreads();   // Qs/Ks no longer needed; region becomes Cs

#pragma unroll
    for (int j = 0; j < 4; j++)
        wmma::store_matrix_sync(&Cs[(wid * 16) * 68 + j * 16], acc[j],
                                68, wmma::mem_row_major);
    __syncthreads();

    const int diag = (kt == qt);
    __half* ebase = g_e + ((size_t)(bh * Sdim) + q0) * Sdim + k0;
    float* lrow = &g_l[bh * Sdim + q0];
#pragma unroll
    for (int i = 0; i < 8; i++) {
        int idx4 = t + i * 128;             // 1024 groups of 4 = 64x64
        int row = idx4 >> 4, c4 = (idx4 & 15) * 4;
        int vlim = diag ? row : 9999;       // valid: col <= vlim
        float4 v = *(const float4*)&Cs[row * 68 + c4];
        float e0 = (c4 + 0 <= vlim) ? exp2f(v.x + bs[c4 + 0]) : 0.f;
        float e1 = (c4 + 1 <= vlim) ? exp2f(v.y + bs[c4 + 1]) : 0.f;
        float e2 = (c4 + 2 <= vlim) ? exp2f(v.z + bs[c4 + 2]) : 0.f;
        float e3 = (c4 + 3 <= vlim) ? exp2f(v.w + bs[c4 + 3]) : 0.f;
        float rs = e0 + e1 + e2 + e3;
        rs += __shfl_xor_sync(0xffffffffu, rs, 1);
        rs += __shfl_xor_sync(0xffffffffu, rs, 2);
        rs += __shfl_xor_sync(0xffffffffu, rs, 4);
        rs += __shfl_xor_sync(0xffffffffu, rs, 8);
        if ((t & 15) == 0) atomicAdd(&lrow[row], rs);
        __half2 h0 = __floats2half2_rn(e0, e1);
        __half2 h1 = __floats2half2_rn(e2, e3);
        uint2 pk = make_uint2(*(uint32_t*)&h0, *(uint32_t*)&h1);
        *(uint2*)&ebase[(size_t)row * Sdim + c4] = pk;
    }
}

// ---------------------------------------------------------------------------
// 4) out = (E @ V) * (1/l) via fp16 wmma; E read directly as fp16.
// ---------------------------------------------------------------------------
__global__ __launch_bounds__(256) void pv_kernel(float* __restrict__ out)
{
    const int qt = gridDim.x - 1 - blockIdx.x;   // heavy tiles first
    const int bh = blockIdx.y;
    const int q0 = qt * 128;
    const int t = threadIdx.x, wid = t >> 5;

    __shared__ __align__(16) char smbuf[128 * 68 * 4];  // 34816 B
    __shared__ float linv[128];
    __half* Ps = (__half*)smbuf;                // [128][72] = 18432 B
    __half* Vs = Ps + 128 * 72;                 // [64][72]  =  9216 B
    float*  Es = (float*)smbuf;                 // [128][68] epilogue staging

    if (t < 128) linv[t] = 1.0f / g_l[bh * Sdim + q0 + t];

    wmma::fragment<wmma::accumulator, 16, 16, 16, float> acc[4];
#pragma unroll
    for (int j = 0; j < 4; j++) wmma::fill_fragment(acc[j], 0.f);

    const __half* erow = g_e + ((size_t)(bh * Sdim) + q0) * Sdim;
    const int nchunks = 2 * qt + 2;
    for (int kc = 0; kc < nchunks; kc++) {
        int k0 = kc * 64;
        const __half* vp = g_vt + ((size_t)bh * Sdim + k0) * Ddim;
        __syncthreads();
#pragma unroll
        for (int i = 0; i < 4; i++) {
            int idx8 = t + i * 256;             // 1024 uint4 = 128x64 halves
            int row = idx8 >> 3, c8 = (idx8 & 7) * 8;
            *(uint4*)&Ps[row * 72 + c8] =
                *(const uint4*)&erow[(size_t)row * Sdim + k0 + c8];
        }
#pragma unroll
        for (int i = 0; i < 2; i++) {
            int idx8 = t + i * 256;             // 512 uint4 = 64x64 halves
            int row = idx8 >> 3, c8 = (idx8 & 7) * 8;
            *(uint4*)&Vs[row * 72 + c8] = *(const uint4*)&vp[row * 64 + c8];
        }
        __syncthreads();

#pragma unroll
        for (int kk = 0; kk < 64; kk += 16) {
            wmma::fragment<wmma::matrix_a, 16, 16, 16, __half, wmma::row_major> a;
            wmma::fragment<wmma::matrix_b, 16, 16, 16, __half, wmma::row_major> b[4];
            wmma::load_matrix_sync(a, &Ps[(wid * 16) * 72 + kk], 72);
#pragma unroll
            for (int j = 0; j < 4; j++)
                wmma::load_matrix_sync(b[j], &Vs[kk * 72 + j * 16], 72);
#pragma unroll
            for (int j = 0; j < 4; j++)
                wmma::mma_sync(acc[j], a, b[j], acc[j]);
        }
    }

    __syncthreads();   // Ps/Vs dead; reuse as Es
#pragma unroll
    for (int j = 0; j < 4; j++)
        wmma::store_matrix_sync(&Es[(wid * 16) * 68 + j * 16], acc[j],
                                68, wmma::mem_row_major);
    __syncthreads();

    float* op = out + ((size_t)bh * Sdim + q0) * Ddim;
#pragma unroll
    for (int i = 0; i < 8; i++) {
        int idx4 = t + i * 256;                 // 2048 float4 = 128x64
        int row = idx4 >> 4, c4 = (idx4 & 15) * 4;
        float4 v = *(const float4*)&Es[row * 68 + c4];
        float s = linv[row];
        v.x *= s; v.y *= s; v.z *= s; v.w *= s;
        *(float4*)&op[(size_t)row * Ddim + c4] = v;
    }
}

// ---------------------------------------------------------------------------
// 5a) zfill: zero the masked (upper-triangle) tiles; no data dependencies.
// ---------------------------------------------------------------------------
__global__ __launch_bounds__(256) void zfill_kernel(float* __restrict__ P)
{
    const int kt = blockIdx.x, qt = blockIdx.y, bh = blockIdx.z;
    if (kt <= qt) return;                        // only masked tiles
    const int t = threadIdx.x;
    long long pbase = ((long long)(bh * Sdim) + qt * 128) * Sdim + kt * 128;
    float4 z = make_float4(0.f, 0.f, 0.f, 0.f);
#pragma unroll
    for (int i = 0; i < 16; i++) {
        int idx4 = t + i * 256;                  // 4096 float4 = 128x128
        int row = idx4 >> 5, c4 = (idx4 & 31) * 4;
        *(float4*)&P[pbase + (long long)row * Sdim + c4] = z;
    }
}

// ---------------------------------------------------------------------------
// 5b) normalize: p = E * (1/l) (fp16 -> fp32), lower-triangle tiles only.
// ---------------------------------------------------------------------------
__global__ __launch_bounds__(256) void normalize_kernel(float* __restrict__ P)
{
    const int kt = blockIdx.x, qt = blockIdx.y, bh = blockIdx.z;
    if (kt > qt) return;
    const int q0 = qt * 128, k0 = kt * 128;
    const int t = threadIdx.x;
    long long pbase = ((long long)(bh * Sdim) + q0) * Sdim + k0;

    __shared__ float linv[128];
    if (t < 128) linv[t] = 1.0f / g_l[bh * Sdim + q0 + t];
    __syncthreads();

    const __half* ebase = g_e + ((size_t)(bh * Sdim) + q0) * Sdim + k0;
#pragma unroll
    for (int i = 0; i < 16; i++) {
        int idx4 = t + i * 256;                 // 4096 float4 = 128x128
        int row = idx4 >> 5, c4 = (idx4 & 31) * 4;
        uint2 pk = *(const uint2*)&ebase[(size_t)row * Sdim + c4];
        __half2 h0 = *(__half2*)&pk.x;
        __half2 h1 = *(__half2*)&pk.y;
        float s = linv[row];
        float4 v;
        v.x = __low2float(h0)  * s;
        v.y = __high2float(h0) * s;
        v.z = __low2float(h1)  * s;
        v.w = __high2float(h1) * s;
        *(float4*)&P[pbase + (long long)row * Sdim + c4] = v;
    }
}

// ---------------------------------------------------------------------------
extern "C" void kernel_launch(void* const* d_in, const int* in_sizes, int n_in,
                              void* d_out, int out_size)
{
    const float* q   = (const float*)d_in[0];
    const float* k   = (const float*)d_in[1];
    const float* v   = (const float*)d_in[2];
    const float* r   = (const float*)d_in[3];
    const float* rb  = (const float*)d_in[4];   // r_bias
    const float* rwb = (const float*)d_in[5];   // r_w_bias
    // d_in[6]: causal mask (structure known, not read)

    float* out = (float*)d_out;
    long long out_elems = (long long)BH * Sdim * Ddim;            // 4,194,304
    long long p_elems   = (long long)BH * Sdim * (long long)Sdim; // 134,217,728

    float* P = nullptr;
    int p_is_output = 0;
    if ((long long)out_size >= out_elems + p_elems) {
        P = out + out_elems;          // p_attn is part of the output
        p_is_output = 1;
    }

    static cudaStream_t s2 = nullptr, s3 = nullptr;
    static cudaEvent_t evFork = nullptr, evA = nullptr, evZ = nullptr,
                       evS = nullptr, evN = nullptr;
    if (!s2) {
        cudaStreamCreateWithFlags(&s2, cudaStreamNonBlocking);
        cudaStreamCreateWithFlags(&s3, cudaStreamNonBlocking);
        cudaEventCreateWithFlags(&evFork, cudaEventDisableTiming);
        cudaEventCreateWithFlags(&evA, cudaEventDisableTiming);
        cudaEventCreateWithFlags(&evZ, cudaEventDisableTiming);
        cudaEventCreateWithFlags(&evS, cudaEventDisableTiming);
        cudaEventCreateWithFlags(&evN, cudaEventDisableTiming);
    }

    dim3 sgrid(Sdim / 64, Sdim / 64, BH);     // scores: (ktile64, qtile64, bh)
    dim3 tgrid(Sdim / 128, Sdim / 128, BH);   // normalize/zfill tiles
    dim3 pvgrid(Sdim / 128, BH);

    // Fork s2 (bias) and s3 (zfill) off the capture-origin stream.
    cudaEventRecord(evFork, 0);
    cudaStreamWaitEvent(s2, evFork, 0);
    bias_kernel<<<NROWS / 256, 256, 0, s2>>>(k, r, rb, rwb);
    cudaEventRecord(evA, s2);

    if (p_is_output) {
        cudaStreamWaitEvent(s3, evFork, 0);
        zfill_kernel<<<tgrid, 256, 0, s3>>>(P);   // no deps; overlaps prep+scores
        cudaEventRecord(evZ, s3);
    }

    prep_kernel<<<(Bdim * Sdim * Hdim * Ddim) / 256, 256>>>(q, k, v, r);
    cudaStreamWaitEvent(0, evA, 0);              // scores needs bias + l zeroed

    scores_exp_kernel<<<sgrid, 128>>>();

    if (p_is_output) {
        cudaEventRecord(evS, 0);
        cudaStreamWaitEvent(s2, evS, 0);
        normalize_kernel<<<tgrid, 256, 0, s2>>>(P);   // ∥ with pv
        cudaEventRecord(evN, s2);
        pv_kernel<<<pvgrid, 256>>>(out);
        cudaStreamWaitEvent(0, evN, 0);
        cudaStreamWaitEvent(0, evZ, 0);
    } else {
        pv_kernel<<<pvgrid, 256>>>(out);
    }
}

// round 16
// speedup vs baseline: 1.2642x; 1.0731x over previous
#include <cuda_runtime.h>
#include <cuda_fp16.h>
#include <mma.h>
#include <cstdint>

using namespace nvcuda;

#define Bdim 2
#define Sdim 2048
#define Hdim 16
#define Ddim 64
#define BH   (Bdim * Hdim)       // 32
#define NROWS (BH * Sdim)        // 65536
#define LOG2E 1.4426950408889634f
#define EXPC2 11.544f            // exp2 offset keeps E in fp16 range

// ---------------------------------------------------------------------------
// Scratch (module scope; in-launch allocation is forbidden)
// ---------------------------------------------------------------------------
__device__ __half g_qt  [(size_t)BH * Sdim * Ddim];   // q [bh][s][d] * 0.125*log2e
__device__ __half g_keff[(size_t)BH * Sdim * Ddim];   // (k + r) [bh][s][d], fp16
__device__ __half g_vt  [(size_t)BH * Sdim * Ddim];   // v [bh][s][d], fp16
__device__ float  g_bias[NROWS];                      // log2-domain bias - EXPC2
__device__ float  g_l   [NROWS];                      // per-q-row sum of E
__device__ __half g_e   [(size_t)BH * Sdim * Sdim];   // E = exp2(S2+bias2), fp16

// ---------------------------------------------------------------------------
// PTX helpers
// ---------------------------------------------------------------------------
#define LDSM_X4(r0, r1, r2, r3, addr) \
    asm volatile("ldmatrix.sync.aligned.m8n8.x4.shared.b16 {%0,%1,%2,%3}, [%4];" \
        : "=r"(r0), "=r"(r1), "=r"(r2), "=r"(r3) : "r"(addr))

#define MMA16816(d, a0, a1, a2, a3, b0, b1) \
    asm volatile("mma.sync.aligned.m16n8k16.row.col.f32.f16.f16.f32 " \
        "{%0,%1,%2,%3}, {%4,%5,%6,%7}, {%8,%9}, {%0,%1,%2,%3};" \
        : "+f"((d)[0]), "+f"((d)[1]), "+f"((d)[2]), "+f"((d)[3]) \
        : "r"(a0), "r"(a1), "r"(a2), "r"(a3), "r"(b0), "r"(b1))

// ---------------------------------------------------------------------------
// 1) transpose + scale + fp16 convert (q pre-scaled into log2 domain)
// ---------------------------------------------------------------------------
__global__ __launch_bounds__(256) void prep_kernel(
    const float* __restrict__ q, const float* __restrict__ k,
    const float* __restrict__ v, const float* __restrict__ r)
{
    int idx = blockIdx.x * 256 + threadIdx.x;        // over B*S*H*D = 2^22
    int d = idx & 63;
    int h = (idx >> 6) & 15;
    int s = (idx >> 10) & 2047;
    int b = idx >> 21;
    int dst = (((b * Hdim + h) * Sdim) + s) * Ddim + d;
    g_qt[dst]   = __float2half_rn(q[idx] * (0.125f * LOG2E));
    g_keff[dst] = __float2half_rn(k[idx] + r[idx]);
    g_vt[dst]   = __float2half_rn(v[idx]);
}

// ---------------------------------------------------------------------------
// 2) per-key bias (log2 domain) + l zeroing
// ---------------------------------------------------------------------------
__global__ __launch_bounds__(256) void bias_kernel(
    const float* __restrict__ k, const float* __restrict__ r,
    const float* __restrict__ r_bias, const float* __restrict__ r_w_bias)
{
    int row = blockIdx.x * 256 + threadIdx.x;        // bh*S + s
    if (row >= NROWS) return;
    int s  = row & 2047;
    int bh = row >> 11;
    int h  = bh & 15;
    int b  = bh >> 4;
    size_t src = ((size_t)(b * Sdim + s) * Hdim + h) * Ddim;
    const float* kp = k + src;
    const float* rp = r + src;
    const float* u  = r_w_bias + h * Ddim;
    const float* w  = r_bias   + h * Ddim;
    float acc = 0.f;
#pragma unroll
    for (int d = 0; d < Ddim; d++) acc += u[d] * kp[d] + w[d] * rp[d];
    g_bias[row] = acc * (0.125f * LOG2E) - EXPC2;
    g_l[row] = 0.f;
}

// ---------------------------------------------------------------------------
// 3) scores + exp2 + row-sums via raw mma.sync with REGISTER epilogue:
//    tile = 128q x 64k, 8 warps x (m16 n64). No accumulator smem round-trip.
//    E = exp2(S + bias2) fp16, masked; l via quad-reduced atomics.
// ---------------------------------------------------------------------------
__global__ __launch_bounds__(256) void scores_exp_kernel()
{
    const int kt = blockIdx.x, qt = blockIdx.y, bh = blockIdx.z;
    if (kt > 2 * qt + 1) return;                 // fully masked 64-wide k tile
    const int q0 = qt * 128, k0 = kt * 64;
    const int t = threadIdx.x, wid = t >> 5, lane = t & 31;

    __shared__ __align__(16) __half Qs[128 * 72];   // 18432 B
    __shared__ __align__(16) __half Ks[64 * 72];    //  9216 B
    __shared__ float bs[64];

    const __half* qptr = g_qt   + ((size_t)bh * Sdim + q0) * Ddim;
    const __half* kptr = g_keff + ((size_t)bh * Sdim + k0) * Ddim;
#pragma unroll
    for (int i = 0; i < 4; i++) {
        int idx8 = t + i * 256;                  // 1024 uint4 = 128x64 halves
        int row = idx8 >> 3, c8 = (idx8 & 7) * 8;
        *(uint4*)&Qs[row * 72 + c8] = *(const uint4*)&qptr[row * 64 + c8];
    }
#pragma unroll
    for (int i = 0; i < 2; i++) {
        int idx8 = t + i * 256;                  // 512 uint4 = 64x64 halves
        int row = idx8 >> 3, c8 = (idx8 & 7) * 8;
        *(uint4*)&Ks[row * 72 + c8] = *(const uint4*)&kptr[row * 64 + c8];
    }
    if (t < 64) bs[t] = g_bias[bh * Sdim + k0 + t];
    __syncthreads();

    const uint32_t qs_base = (uint32_t)__cvta_generic_to_shared(Qs);
    const uint32_t ks_base = (uint32_t)__cvta_generic_to_shared(Ks);
    const int m0 = wid * 16;
    const int lr = lane & 7, sel = lane >> 3;    // ldmatrix lane roles

    float acc[8][4];
#pragma unroll
    for (int j = 0; j < 8; j++)
#pragma unroll
        for (int c = 0; c < 4; c++) acc[j][c] = 0.f;

#pragma unroll
    for (int kk = 0; kk < 64; kk += 16) {
        uint32_t a0, a1, a2, a3;
        // A tiles: sel0=(r0-7,k0-7) sel1=(r8-15,k0-7) sel2=(r0-7,k8-15) sel3=(r8-15,k8-15)
        uint32_t a_addr = qs_base +
            (uint32_t)(((m0 + ((sel & 1) << 3) + lr) * 72 + kk + ((sel >> 1) << 3)) * 2);
        LDSM_X4(a0, a1, a2, a3, a_addr);
#pragma unroll
        for (int jj = 0; jj < 4; jj++) {
            int n_base = jj * 16;
            uint32_t b0, b1, b2, b3;
            // B tiles: sel0=(n0-7,k0-7) sel1=(n0-7,k8-15) sel2=(n8-15,k0-7) sel3=(n8-15,k8-15)
            uint32_t b_addr = ks_base +
                (uint32_t)(((n_base + ((sel >> 1) << 3) + lr) * 72 + kk + ((sel & 1) << 3)) * 2);
            LDSM_X4(b0, b1, b2, b3, b_addr);
            MMA16816(acc[2 * jj],     a0, a1, a2, a3, b0, b1);
            MMA16816(acc[2 * jj + 1], a0, a1, a2, a3, b2, b3);
        }
    }

    // Register epilogue: bias + causal mask + exp2, half2 stores, quad row-sums.
    const int r0 = m0 + (lane >> 2);             // rows r0 and r0+8
    const int cb = (lane & 3) * 2;
    const int v0 = q0 + r0 - k0;                 // valid col <= v0 (row r0)
    const int v1 = v0 + 8;                       // row r0+8
    __half* ebase = g_e + ((size_t)(bh * Sdim) + q0) * Sdim + k0;
    float rs0 = 0.f, rs1 = 0.f;
#pragma unroll
    for (int j = 0; j < 8; j++) {
        int col = j * 8 + cb;
        float b0 = bs[col], b1 = bs[col + 1];
        float e00 = (col     <= v0) ? exp2f(acc[j][0] + b0) : 0.f;
        float e01 = (col + 1 <= v0) ? exp2f(acc[j][1] + b1) : 0.f;
        float e10 = (col     <= v1) ? exp2f(acc[j][2] + b0) : 0.f;
        float e11 = (col + 1 <= v1) ? exp2f(acc[j][3] + b1) : 0.f;
        rs0 += e00 + e01;
        rs1 += e10 + e11;
        *(__half2*)&ebase[(size_t)r0 * Sdim + col]       = __floats2half2_rn(e00, e01);
        *(__half2*)&ebase[(size_t)(r0 + 8) * Sdim + col] = __floats2half2_rn(e10, e11);
    }
    rs0 += __shfl_xor_sync(0xffffffffu, rs0, 1);
    rs0 += __shfl_xor_sync(0xffffffffu, rs0, 2);
    rs1 += __shfl_xor_sync(0xffffffffu, rs1, 1);
    rs1 += __shfl_xor_sync(0xffffffffu, rs1, 2);
    if ((lane & 3) == 0) {
        float* lrow = &g_l[bh * Sdim + q0];
        atomicAdd(&lrow[r0], rs0);
        atomicAdd(&lrow[r0 + 8], rs1);
    }
}

// ---------------------------------------------------------------------------
// 4) out = (E @ V) * (1/l) via fp16 wmma; E read directly as fp16.
// ---------------------------------------------------------------------------
__global__ __launch_bounds__(256) void pv_kernel(float* __restrict__ out)
{
    const int qt = gridDim.x - 1 - blockIdx.x;   // heavy tiles first
    const int bh = blockIdx.y;
    const int q0 = qt * 128;
    const int t = threadIdx.x, wid = t >> 5;

    __shared__ __align__(16) char smbuf[128 * 68 * 4];  // 34816 B
    __shared__ float linv[128];
    __half* Ps = (__half*)smbuf;                // [128][72] = 18432 B
    __half* Vs = Ps + 128 * 72;                 // [64][72]  =  9216 B
    float*  Es = (float*)smbuf;                 // [128][68] epilogue staging

    if (t < 128) linv[t] = 1.0f / g_l[bh * Sdim + q0 + t];

    wmma::fragment<wmma::accumulator, 16, 16, 16, float> acc[4];
#pragma unroll
    for (int j = 0; j < 4; j++) wmma::fill_fragment(acc[j], 0.f);

    const __half* erow = g_e + ((size_t)(bh * Sdim) + q0) * Sdim;
    const int nchunks = 2 * qt + 2;
    for (int kc = 0; kc < nchunks; kc++) {
        int k0 = kc * 64;
        const __half* vp = g_vt + ((size_t)bh * Sdim + k0) * Ddim;
        __syncthreads();
#pragma unroll
        for (int i = 0; i < 4; i++) {
            int idx8 = t + i * 256;             // 1024 uint4 = 128x64 halves
            int row = idx8 >> 3, c8 = (idx8 & 7) * 8;
            *(uint4*)&Ps[row * 72 + c8] =
                *(const uint4*)&erow[(size_t)row * Sdim + k0 + c8];
        }
#pragma unroll
        for (int i = 0; i < 2; i++) {
            int idx8 = t + i * 256;             // 512 uint4 = 64x64 halves
            int row = idx8 >> 3, c8 = (idx8 & 7) * 8;
            *(uint4*)&Vs[row * 72 + c8] = *(const uint4*)&vp[row * 64 + c8];
        }
        __syncthreads();

#pragma unroll
        for (int kk = 0; kk < 64; kk += 16) {
            wmma::fragment<wmma::matrix_a, 16, 16, 16, __half, wmma::row_major> a;
            wmma::fragment<wmma::matrix_b, 16, 16, 16, __half, wmma::row_major> b[4];
            wmma::load_matrix_sync(a, &Ps[(wid * 16) * 72 + kk], 72);
#pragma unroll
            for (int j = 0; j < 4; j++)
                wmma::load_matrix_sync(b[j], &Vs[kk * 72 + j * 16], 72);
#pragma unroll
            for (int j = 0; j < 4; j++)
                wmma::mma_sync(acc[j], a, b[j], acc[j]);
        }
    }

    __syncthreads();   // Ps/Vs dead; reuse as Es
#pragma unroll
    for (int j = 0; j < 4; j++)
        wmma::store_matrix_sync(&Es[(wid * 16) * 68 + j * 16], acc[j],
                                68, wmma::mem_row_major);
    __syncthreads();

    float* op = out + ((size_t)bh * Sdim + q0) * Ddim;
#pragma unroll
    for (int i = 0; i < 8; i++) {
        int idx4 = t + i * 256;                 // 2048 float4 = 128x64
        int row = idx4 >> 4, c4 = (idx4 & 15) * 4;
        float4 v = *(const float4*)&Es[row * 68 + c4];
        float s = linv[row];
        v.x *= s; v.y *= s; v.z *= s; v.w *= s;
        *(float4*)&op[(size_t)row * Ddim + c4] = v;
    }
}

// ---------------------------------------------------------------------------
// 5a) zfill: zero the masked (upper-triangle) tiles; no data dependencies.
// ---------------------------------------------------------------------------
__global__ __launch_bounds__(256) void zfill_kernel(float* __restrict__ P)
{
    const int kt = blockIdx.x, qt = blockIdx.y, bh = blockIdx.z;
    if (kt <= qt) return;                        // only masked tiles
    const int t = threadIdx.x;
    long long pbase = ((long long)(bh * Sdim) + qt * 128) * Sdim + kt * 128;
    float4 z = make_float4(0.f, 0.f, 0.f, 0.f);
#pragma unroll
    for (int i = 0; i < 16; i++) {
        int idx4 = t + i * 256;                  // 4096 float4 = 128x128
        int row = idx4 >> 5, c4 = (idx4 & 31) * 4;
        *(float4*)&P[pbase + (long long)row * Sdim + c4] = z;
    }
}

// ---------------------------------------------------------------------------
// 5b) normalize: p = E * (1/l) (fp16 -> fp32), lower-triangle tiles only.
// ---------------------------------------------------------------------------
__global__ __launch_bounds__(256) void normalize_kernel(float* __restrict__ P)
{
    const int kt = blockIdx.x, qt = blockIdx.y, bh = blockIdx.z;
    if (kt > qt) return;
    const int q0 = qt * 128, k0 = kt * 128;
    const int t = threadIdx.x;
    long long pbase = ((long long)(bh * Sdim) + q0) * Sdim + k0;

    __shared__ float linv[128];
    if (t < 128) linv[t] = 1.0f / g_l[bh * Sdim + q0 + t];
    __syncthreads();

    const __half* ebase = g_e + ((size_t)(bh * Sdim) + q0) * Sdim + k0;
#pragma unroll
    for (int i = 0; i < 16; i++) {
        int idx4 = t + i * 256;                 // 4096 float4 = 128x128
        int row = idx4 >> 5, c4 = (idx4 & 31) * 4;
        uint2 pk = *(const uint2*)&ebase[(size_t)row * Sdim + c4];
        __half2 h0 = *(__half2*)&pk.x;
        __half2 h1 = *(__half2*)&pk.y;
        float s = linv[row];
        float4 v;
        v.x = __low2float(h0)  * s;
        v.y = __high2float(h0) * s;
        v.z = __low2float(h1)  * s;
        v.w = __high2float(h1) * s;
        *(float4*)&P[pbase + (long long)row * Sdim + c4] = v;
    }
}

// ---------------------------------------------------------------------------
extern "C" void kernel_launch(void* const* d_in, const int* in_sizes, int n_in,
                              void* d_out, int out_size)
{
    const float* q   = (const float*)d_in[0];
    const float* k   = (const float*)d_in[1];
    const float* v   = (const float*)d_in[2];
    const float* r   = (const float*)d_in[3];
    const float* rb  = (const float*)d_in[4];   // r_bias
    const float* rwb = (const float*)d_in[5];   // r_w_bias
    // d_in[6]: causal mask (structure known, not read)

    float* out = (float*)d_out;
    long long out_elems = (long long)BH * Sdim * Ddim;            // 4,194,304
    long long p_elems   = (long long)BH * Sdim * (long long)Sdim; // 134,217,728

    float* P = nullptr;
    int p_is_output = 0;
    if ((long long)out_size >= out_elems + p_elems) {
        P = out + out_elems;          // p_attn is part of the output
        p_is_output = 1;
    }

    static cudaStream_t s2 = nullptr, s3 = nullptr;
    static cudaEvent_t evFork = nullptr, evA = nullptr, evZ = nullptr,
                       evS = nullptr, evN = nullptr;
    if (!s2) {
        cudaStreamCreateWithFlags(&s2, cudaStreamNonBlocking);
        cudaStreamCreateWithFlags(&s3, cudaStreamNonBlocking);
        cudaEventCreateWithFlags(&evFork, cudaEventDisableTiming);
        cudaEventCreateWithFlags(&evA, cudaEventDisableTiming);
        cudaEventCreateWithFlags(&evZ, cudaEventDisableTiming);
        cudaEventCreateWithFlags(&evS, cudaEventDisableTiming);
        cudaEventCreateWithFlags(&evN, cudaEventDisableTiming);
    }

    dim3 sgrid(Sdim / 64, Sdim / 128, BH);    // scores: (ktile64, qtile128, bh)
    dim3 tgrid(Sdim / 128, Sdim / 128, BH);   // normalize/zfill tiles
    dim3 pvgrid(Sdim / 128, BH);

    // Fork s2 (bias) and s3 (zfill) off the capture-origin stream.
    cudaEventRecord(evFork, 0);
    cudaStreamWaitEvent(s2, evFork, 0);
    bias_kernel<<<NROWS / 256, 256, 0, s2>>>(k, r, rb, rwb);
    cudaEventRecord(evA, s2);

    if (p_is_output) {
        cudaStreamWaitEvent(s3, evFork, 0);
        zfill_kernel<<<tgrid, 256, 0, s3>>>(P);   // no deps; overlaps prep+scores
        cudaEventRecord(evZ, s3);
    }

    prep_kernel<<<(Bdim * Sdim * Hdim * Ddim) / 256, 256>>>(q, k, v, r);
    cudaStreamWaitEvent(0, evA, 0);              // scores needs bias + l zeroed

    scores_exp_kernel<<<sgrid, 256>>>();

    if (p_is_output) {
        cudaEventRecord(evS, 0);
        cudaStreamWaitEvent(s2, evS, 0);
        normalize_kernel<<<tgrid, 256, 0, s2>>>(P);   // ∥ with pv
        cudaEventRecord(evN, s2);
        pv_kernel<<<pvgrid, 256>>>(out);
        cudaStreamWaitEvent(0, evN, 0);
        cudaStreamWaitEvent(0, evZ, 0);
    } else {
        pv_kernel<<<pvgrid, 256>>>(out);
    }
}